// round 17
// baseline (speedup 1.0000x reference)
#include <cuda_runtime.h>
#include <cuda_fp16.h>
#include <cstdint>
#include <math.h>

#define BATCH 16
#define SEQ   512
#define NI    32
#define NHEAD 8
#define NH    512
#define NO    64
#define MROWS (BATCH*SEQ)      // 8192
#define VDIM  (NHEAD*NI)       // 256
#define EPSV  1e-5f
#define SLOPE 0.05f
#define NPART 64

// ---------------- scratch ----------------
__device__ float    g_En  [16*8*512];
__device__ uint32_t g_Xthi[(size_t)16*256*256], g_Xtlo[(size_t)16*256*256];
__device__ uint32_t g_Gh  [(size_t)16*512*256];
__device__ uint32_t g_Vh  [(size_t)8192*128];
__device__ uint32_t g_W1h [512*128];
__device__ uint32_t g_W2h [512*256];
__device__ uint32_t g_W3hi[64*256], g_W3lo[64*256];
__device__ uint32_t g_Axh [(size_t)8192*256];
__device__ float g_Y1[(size_t)MROWS * NH];
__device__ float g_Y2[(size_t)MROWS * NH];
__device__ float g_Y3[(size_t)MROWS * NO];
__device__ float g_pS [NPART * NH];
__device__ float g_pS2[NPART * NH];
__device__ float g_scale[NH];
__device__ float g_shift[NH];
__device__ int   g_cnt = 0;

// ---------------- helpers ----------------
__device__ __forceinline__ void split_pair_h(float v0, float v1, uint32_t& hi, uint32_t& lo) {
    __half h0 = __float2half(v0);
    __half h1 = __float2half(v1);
    float r0 = v0 - __half2float(h0);
    float r1 = v1 - __half2float(h1);
    __half l0 = __float2half(r0);
    __half l1 = __float2half(r1);
    hi = ((uint32_t)__half_as_ushort(h1) << 16) | __half_as_ushort(h0);
    lo = ((uint32_t)__half_as_ushort(l1) << 16) | __half_as_ushort(l0);
}
__device__ __forceinline__ uint32_t pack_h(float v0, float v1) {
    __half h0 = __float2half(v0);
    __half h1 = __float2half(v1);
    return ((uint32_t)__half_as_ushort(h1) << 16) | __half_as_ushort(h0);
}

__device__ __forceinline__ void mma_f16(float* d, const uint32_t* a, const uint32_t* b) {
    asm volatile(
        "mma.sync.aligned.m16n8k16.row.col.f32.f16.f16.f32 "
        "{%0,%1,%2,%3}, {%4,%5,%6,%7}, {%8,%9}, {%0,%1,%2,%3};"
        : "+f"(d[0]), "+f"(d[1]), "+f"(d[2]), "+f"(d[3])
        : "r"(a[0]), "r"(a[1]), "r"(a[2]), "r"(a[3]), "r"(b[0]), "r"(b[1]));
}

__device__ __forceinline__ void ldsm4(uint32_t* r, uint32_t addr) {
    asm volatile("ldmatrix.sync.aligned.m8n8.x4.shared.b16 {%0,%1,%2,%3}, [%4];"
        : "=r"(r[0]), "=r"(r[1]), "=r"(r[2]), "=r"(r[3]) : "r"(addr));
}

__device__ __forceinline__ uint32_t smem_u32(const void* p) {
    uint32_t a;
    asm("{ .reg .u64 t; cvta.to.shared.u64 t, %1; cvt.u32.u64 %0, t; }" : "=r"(a) : "l"(p));
    return a;
}
__device__ __forceinline__ void cp_async16(uint32_t saddr, const void* gptr) {
    asm volatile("cp.async.cg.shared.global [%0], [%1], 16;" :: "r"(saddr), "l"(gptr));
}
#define CP_COMMIT() asm volatile("cp.async.commit_group;" ::: "memory")
#define CP_WAIT0()  asm volatile("cp.async.wait_group 0;" ::: "memory")

// ---------------- prep_all ----------------
__global__ void __launch_bounds__(256) prep_all_kernel(
    const float* __restrict__ x, const float* __restrict__ Q,
    float* __restrict__ En,
    uint32_t* __restrict__ Xthi, uint32_t* __restrict__ Xtlo,
    const float* __restrict__ W1, uint32_t* __restrict__ W1h,
    const float* __restrict__ W2, uint32_t* __restrict__ W2h,
    const float* __restrict__ W3, uint32_t* __restrict__ W3hi, uint32_t* __restrict__ W3lo,
    uint32_t* __restrict__ Gh)
{
    const int blk = blockIdx.x;
    const int tid = threadIdx.x;

    __shared__ float sEm[8][128];
    __shared__ float sQ[8][4];
    __shared__ uint32_t shi[256][8], slo[256][8];
    __shared__ float pn3[64][5];
    __shared__ float pm3[128][4];

    if (blk >= 168) {
        const int g  = blk - 168;
        const int b  = g >> 3, nt = g & 7;
        const int n = tid & 63, mq = tid >> 6;

        if (tid < 64) {
            const float* xp = x + ((size_t)b*512 + nt*64 + tid)*32;
            pn3[tid][0] = xp[0]; pn3[tid][1] = xp[1]; pn3[tid][2] = xp[2];
        }
        for (int mc = 0; mc < 4; mc++) {
            __syncthreads();
            if (tid < 128) {
                const float* xp = x + ((size_t)b*512 + mc*128 + tid)*32;
                pm3[tid][0] = xp[0]; pm3[tid][1] = xp[1]; pm3[tid][2] = xp[2];
            }
            __syncthreads();
            float px = pn3[n][0], py = pn3[n][1], pz = pn3[n][2];
            uint32_t outh[16];
            #pragma unroll
            for (int j = 0; j < 16; j++) {
                int ml = mq*32 + j*2;
                float dx0 = px - pm3[ml][0],   dy0 = py - pm3[ml][1],   dz0 = pz - pm3[ml][2];
                float dx1 = px - pm3[ml+1][0], dy1 = py - pm3[ml+1][1], dz1 = pz - pm3[ml+1][2];
                float e0 = __expf(-(dx0*dx0 + dy0*dy0 + dz0*dz0));
                float e1 = __expf(-(dx1*dx1 + dy1*dy1 + dz1*dz1));
                outh[j] = pack_h(e0, e1);
            }
            size_t base = ((size_t)b*512 + nt*64 + n)*256 + mc*64 + mq*16;
            #pragma unroll
            for (int j4 = 0; j4 < 4; j4++)
                ((uint4*)(Gh + base))[j4] = make_uint4(outh[j4*4], outh[j4*4+1], outh[j4*4+2], outh[j4*4+3]);
        }
        return;
    }

    if (blk >= 64) {
        int widx = blk - 64;
        if (widx < 32) {
            int p = widx * 2048 + tid;
            #pragma unroll
            for (int j = 0; j < 8; j++, p += 256) {
                float2 v = ((const float2*)W1)[p];
                W1h[p] = pack_h(v.x, v.y);
            }
        } else if (widx < 96) {
            int p = (widx - 32) * 2048 + tid;
            #pragma unroll
            for (int j = 0; j < 8; j++, p += 256) {
                float2 v = ((const float2*)W2)[p];
                W2h[p] = pack_h(v.x, v.y);
            }
        } else {
            int p = (widx - 96) * 2048 + tid;
            #pragma unroll
            for (int j = 0; j < 8; j++, p += 256) {
                float2 v = ((const float2*)W3)[p];
                uint32_t h, l; split_pair_h(v.x, v.y, h, l);
                W3hi[p] = h; W3lo[p] = l;
            }
        }
        return;
    }

    const int b = blk >> 2, chunk = blk & 3;

    if (tid < 8) {
        float a = Q[tid*3+0], bq = Q[tid*3+1], cq = Q[tid*3+2];
        sQ[tid][0] = a; sQ[tid][1] = bq; sQ[tid][2] = cq;
        sQ[tid][3] = a*a + bq*bq + cq*cq;
    }
    __syncthreads();

    if (tid < 128) {
        int m = chunk*128 + tid;
        const float* xp = x + ((size_t)b*512 + m)*32;
        float px = xp[0], py = xp[1], pz = xp[2];
        #pragma unroll
        for (int h = 0; h < 8; h++) {
            float dot = px*sQ[h][0] + py*sQ[h][1] + pz*sQ[h][2];
            float em = __expf(-2.f*dot);
            float en = __expf(2.f*dot - sQ[h][3]);
            sEm[h][tid] = em;
            En[((size_t)b*8 + h)*512 + m] = en;
        }
    }
    __syncthreads();

    const int c = tid, h = c >> 5, i = c & 31;
    for (int grp = 0; grp < 8; grp++) {
        #pragma unroll
        for (int j = 0; j < 8; j++) {
            int mloc = (grp*8 + j)*2;
            int m = chunk*128 + mloc;
            float v0 = sEm[h][mloc]   * x[((size_t)b*512 + m  )*32 + i];
            float v1 = sEm[h][mloc+1] * x[((size_t)b*512 + m+1)*32 + i];
            uint32_t hh, ll; split_pair_h(v0, v1, hh, ll);
            shi[c][j] = hh; slo[c][j] = ll;
        }
        __syncthreads();
        int cc = tid >> 3, j2 = tid & 7;
        #pragma unroll
        for (int rep = 0; rep < 8; rep++) {
            int ccc = cc + rep*32;
            size_t addr = ((size_t)b*256 + ccc)*256 + chunk*64 + grp*8 + j2;
            Xthi[addr] = shi[ccc][j2];
            Xtlo[addr] = slo[ccc][j2];
        }
        __syncthreads();
    }
}

// ================= GEMM machinery =================
#define RSU 20
#define TN  64
#define NFRAG (TN/16)
#define ASZ (128*RSU)
#define BSZ (TN*RSU)

// ---------------- vgemm ----------------
__global__ void __launch_bounds__(256, 3) vgemm_kernel(
    const uint32_t* __restrict__ Gh_g,
    const uint32_t* __restrict__ Bhi_g, const uint32_t* __restrict__ Blo_g,
    const float* __restrict__ En, const float* __restrict__ x,
    uint32_t* __restrict__ Vh)
{
    constexpr int KE = 512, K2 = KE/2;
    extern __shared__ uint32_t smem_u[];
    const uint32_t sbase = smem_u32(smem_u);
    const uint32_t bA  = sbase;
    const uint32_t bBh = sbase + 2*ASZ*4;
    const uint32_t bBl = sbase + (2*ASZ + 2*BSZ)*4;

    const int tid = threadIdx.x, wid = tid >> 5, lane = tid & 31;
    const int wm = (wid >> 1) * 32, wn = (wid & 1) * (TN/2);
    const int l4 = lane >> 2, lk = lane & 3;
    const int rowA = lane & 15, colA = (lane >> 4) * 4;
    const int rowB = ((lane >> 4) & 1) * 8 + (lane & 7);
    const int colB = ((lane >> 3) & 1) * 4;
    const int b = blockIdx.z;
    const int m0 = blockIdx.y * 128, c0 = blockIdx.x * TN;

    const uint32_t* A_g  = Gh_g + (size_t)b*512*K2;
    const uint32_t* Bh_g = Bhi_g + (size_t)b*256*K2;
    const uint32_t* Bl_g = Blo_g + (size_t)b*256*K2;

    float acc[2][NFRAG][4];
    #pragma unroll
    for (int a = 0; a < 2; a++)
        #pragma unroll
        for (int q = 0; q < NFRAG; q++)
            { acc[a][q][0]=0.f; acc[a][q][1]=0.f; acc[a][q][2]=0.f; acc[a][q][3]=0.f; }

    auto issue = [&](int t) {
        int buf = t & 1;
        #pragma unroll
        for (int j = 0; j < 2; j++) {
            int lin = tid + j*256; int r = lin >> 2, q = lin & 3;
            uint32_t off = (uint32_t)(buf*ASZ + r*RSU + q*4) * 4;
            size_t ao = (size_t)(m0 + r)*K2 + t*16 + q*4;
            cp_async16(bA + off, A_g + ao);
        }
        {
            int r = tid >> 2, q = tid & 3;
            uint32_t off = (uint32_t)(buf*BSZ + r*RSU + q*4) * 4;
            size_t bo = (size_t)(c0 + r)*K2 + t*16 + q*4;
            cp_async16(bBh + off, Bh_g + bo);
            cp_async16(bBl + off, Bl_g + bo);
        }
        CP_COMMIT();
    };

    auto compute = [&](int buf) {
        #pragma unroll
        for (int kk = 0; kk < 2; kk++) {
            uint32_t ah[2][4];
            #pragma unroll
            for (int mi = 0; mi < 2; mi++) {
                uint32_t off = (uint32_t)(buf*ASZ + (wm + mi*16 + rowA)*RSU + kk*8 + colA) * 4;
                ldsm4(ah[mi], bA + off);
            }
            #pragma unroll
            for (int np = 0; np < NFRAG/2; np++) {
                uint32_t off = (uint32_t)(buf*BSZ + (wn + np*16 + rowB)*RSU + kk*8 + colB) * 4;
                uint32_t th[4], tl[4];
                ldsm4(th, bBh + off);
                ldsm4(tl, bBl + off);
                #pragma unroll
                for (int sub = 0; sub < 2; sub++) {
                    int ni = np*2 + sub;
                    uint32_t bhp[2] = {th[sub*2], th[sub*2+1]};
                    uint32_t blp[2] = {tl[sub*2], tl[sub*2+1]};
                    #pragma unroll
                    for (int mi = 0; mi < 2; mi++) {
                        mma_f16(acc[mi][ni], ah[mi], bhp);
                        mma_f16(acc[mi][ni], ah[mi], blp);
                    }
                }
            }
        }
    };

    const int T = KE / 32;
    issue(0);
    for (int t = 0; t < T; t++) {
        CP_WAIT0();
        __syncthreads();
        if (t + 1 < T) issue(t + 1);
        compute(t & 1);
    }

    #pragma unroll
    for (int mi = 0; mi < 2; mi++) {
        #pragma unroll
        for (int ni = 0; ni < NFRAG; ni++) {
            int n0 = m0 + wm + mi*16 + l4;
            int cc = c0 + wn + ni*8 + lk*2;
            int h = cc >> 5, il = cc & 31;
            float en0 = En[((size_t)b*8 + h)*512 + n0];
            float en1 = En[((size_t)b*8 + h)*512 + n0 + 8];
            float v00 = acc[mi][ni][0]*en0, v01 = acc[mi][ni][1]*en0;
            float v10 = acc[mi][ni][2]*en1, v11 = acc[mi][ni][3]*en1;
            if (il < 3) {
                v00 -= x[((size_t)b*512 + n0  )*32 + il];
                v10 -= x[((size_t)b*512 + n0+8)*32 + il];
            }
            if (il + 1 < 3) {
                v01 -= x[((size_t)b*512 + n0  )*32 + il + 1];
                v11 -= x[((size_t)b*512 + n0+8)*32 + il + 1];
            }
            size_t r0 = ((size_t)b*512 + n0)*128 + (cc >> 1);
            size_t r1 = ((size_t)b*512 + n0 + 8)*128 + (cc >> 1);
            Vh[r0] = pack_h(v00, v01);
            Vh[r1] = pack_h(v10, v11);
        }
    }
}

// ---------------- gemm_big: TM=256 x TNB=128, 1 MMA, fused stats + last-block finalize ----------------
#define TNB  128
#define NFB  (TNB/16)
#define ASZB (256*RSU)
#define BSZB (128*RSU)

__global__ void __launch_bounds__(512, 1) gemm_big_kernel(
    const uint32_t* __restrict__ A_g,
    const uint32_t* __restrict__ Bh_g,
    const float* __restrict__ bias, float* __restrict__ Y,
    float* __restrict__ pS, float* __restrict__ pS2,
    const float* __restrict__ gc, const float* __restrict__ btc,
    float* __restrict__ scale, float* __restrict__ shift,
    int K, int C)
{
    extern __shared__ uint32_t smem_u[];
    const uint32_t sbase = smem_u32(smem_u);
    const uint32_t bA  = sbase;
    const uint32_t bBh = sbase + 2*ASZB*4;

    const int tid = threadIdx.x, wid = tid >> 5, lane = tid & 31;
    const int wm = (wid >> 1) * 32;
    const int wn = (wid & 1) * 64;
    const int mw = wid >> 1;
    const int l4 = lane >> 2, lk = lane & 3;
    const int rowA = lane & 15, colA = (lane >> 4) * 4;
    const int rowB = ((lane >> 4) & 1) * 8 + (lane & 7);
    const int colB = ((lane >> 3) & 1) * 4;
    const int m0 = blockIdx.y * 256, c0 = blockIdx.x * TNB;
    const int K2 = K >> 1;

    float acc[2][NFB][4];
    #pragma unroll
    for (int a = 0; a < 2; a++)
        #pragma unroll
        for (int q = 0; q < NFB; q++)
            { acc[a][q][0]=0.f; acc[a][q][1]=0.f; acc[a][q][2]=0.f; acc[a][q][3]=0.f; }

    auto issue = [&](int t) {
        int buf = t & 1;
        #pragma unroll
        for (int j = 0; j < 2; j++) {
            int lin = tid + j*512; int r = lin >> 2, q = lin & 3;
            uint32_t off = (uint32_t)(buf*ASZB + r*RSU + q*4) * 4;
            size_t ao = (size_t)(m0 + r)*K2 + t*16 + q*4;
            cp_async16(bA + off, A_g + ao);
        }
        {
            int r = tid >> 2, q = tid & 3;
            uint32_t off = (uint32_t)(buf*BSZB + r*RSU + q*4) * 4;
            size_t bo = (size_t)(c0 + r)*K2 + t*16 + q*4;
            cp_async16(bBh + off, Bh_g + bo);
        }
        CP_COMMIT();
    };

    auto compute = [&](int buf) {
        #pragma unroll
        for (int kk = 0; kk < 2; kk++) {
            uint32_t ah[2][4];
            #pragma unroll
            for (int mi = 0; mi < 2; mi++) {
                uint32_t off = (uint32_t)(buf*ASZB + (wm + mi*16 + rowA)*RSU + kk*8 + colA) * 4;
                ldsm4(ah[mi], bA + off);
            }
            #pragma unroll
            for (int np = 0; np < NFB/2; np++) {
                uint32_t off = (uint32_t)(buf*BSZB + (wn + np*16 + rowB)*RSU + kk*8 + colB) * 4;
                uint32_t th[4];
                ldsm4(th, bBh + off);
                #pragma unroll
                for (int sub = 0; sub < 2; sub++) {
                    int ni = np*2 + sub;
                    uint32_t bhp[2] = {th[sub*2], th[sub*2+1]};
                    #pragma unroll
                    for (int mi = 0; mi < 2; mi++)
                        mma_f16(acc[mi][ni], ah[mi], bhp);
                }
            }
        }
    };

    const int T = K / 32;
    issue(0);
    for (int t = 0; t < T; t++) {
        CP_WAIT0();
        __syncthreads();
        if (t + 1 < T) issue(t + 1);
        compute(t & 1);
    }
    __syncthreads();

    float* sbufS  = (float*)smem_u;
    float* sbufS2 = sbufS + 8*TNB;
    __shared__ int isLast;

    #pragma unroll
    for (int ni = 0; ni < NFB; ni++) {
        int col = c0 + wn + ni*8 + lk*2;
        float2 b2 = *(const float2*)(bias + col);
        float s0 = 0.f, s1 = 0.f, q0 = 0.f, q1 = 0.f;
        #pragma unroll
        for (int mi = 0; mi < 2; mi++) {
            int row = m0 + wm + mi*16 + l4;
            float e0 = acc[mi][ni][0] + b2.x;
            float e1 = acc[mi][ni][1] + b2.y;
            float e2 = acc[mi][ni][2] + b2.x;
            float e3 = acc[mi][ni][3] + b2.y;
            *(float2*)(Y + (size_t)row * C + col)       = make_float2(e0, e1);
            *(float2*)(Y + (size_t)(row + 8) * C + col) = make_float2(e2, e3);
            s0 += e0 + e2; s1 += e1 + e3;
            q0 += e0*e0 + e2*e2; q1 += e1*e1 + e3*e3;
        }
        #pragma unroll
        for (int off = 16; off >= 4; off >>= 1) {
            s0 += __shfl_down_sync(0xffffffffu, s0, off);
            s1 += __shfl_down_sync(0xffffffffu, s1, off);
            q0 += __shfl_down_sync(0xffffffffu, q0, off);
            q1 += __shfl_down_sync(0xffffffffu, q1, off);
        }
        if (lane < 4) {
            int cb = wn + ni*8 + lk*2;
            sbufS [mw*TNB + cb]     = s0;
            sbufS [mw*TNB + cb + 1] = s1;
            sbufS2[mw*TNB + cb]     = q0;
            sbufS2[mw*TNB + cb + 1] = q1;
        }
    }
    __syncthreads();
    if (tid < TNB) {
        float s = 0.f, q = 0.f;
        #pragma unroll
        for (int r = 0; r < 8; r++) { s += sbufS[r*TNB + tid]; q += sbufS2[r*TNB + tid]; }
        pS [blockIdx.y * C + c0 + tid] = s;
        pS2[blockIdx.y * C + c0 + tid] = q;
        __threadfence();
    }
    __syncthreads();
    if (tid == 0) {
        int t = atomicAdd(&g_cnt, 1);
        isLast = (t == (int)(gridDim.x * gridDim.y) - 1);
    }
    __syncthreads();
    if (isLast) {
        __threadfence();
        const int npart = gridDim.y;
        for (int c = tid; c < C; c += 512) {
            float s = 0.f, q = 0.f;
            for (int p = 0; p < npart; p++) {
                s += pS [p * C + c];
                q += pS2[p * C + c];
            }
            float invM = 1.f / (float)MROWS;
            float mean = s * invM;
            float var  = fmaf(-mean, mean, q * invM);
            float inv  = rsqrtf(var + EPSV);
            float scv  = gc[c] * inv;
            scale[c] = scv;
            shift[c] = fmaf(-mean, scv, btc[c]);
        }
        if (tid == 0) g_cnt = 0;
    }
}

// ---------------- gemm_ps (TN=64, B pair) layer 3 + last-block finalize ----------------
__global__ void __launch_bounds__(256, 3) gemm_ps_kernel(
    const uint32_t* __restrict__ A_g,
    const uint32_t* __restrict__ Bh_g, const uint32_t* __restrict__ Bl_g,
    const float* __restrict__ bias, float* __restrict__ Y,
    float* __restrict__ pS, float* __restrict__ pS2,
    const float* __restrict__ gc, const float* __restrict__ btc,
    float* __restrict__ scale, float* __restrict__ shift,
    int K, int C)
{
    extern __shared__ uint32_t smem_u[];
    const uint32_t sbase = smem_u32(smem_u);
    const uint32_t bA  = sbase;
    const uint32_t bBh = sbase + 2*ASZ*4;
    const uint32_t bBl = sbase + (2*ASZ + 2*BSZ)*4;

    const int tid = threadIdx.x, wid = tid >> 5, lane = tid & 31;
    const int wm = (wid >> 1) * 32, wn = (wid & 1) * (TN/2);
    const int mw = wid >> 1;
    const int l4 = lane >> 2, lk = lane & 3;
    const int rowA = lane & 15, colA = (lane >> 4) * 4;
    const int rowB = ((lane >> 4) & 1) * 8 + (lane & 7);
    const int colB = ((lane >> 3) & 1) * 4;
    const int m0 = blockIdx.y * 128, c0 = blockIdx.x * TN;
    const int K2 = K >> 1;

    float acc[2][NFRAG][4];
    #pragma unroll
    for (int a = 0; a < 2; a++)
        #pragma unroll
        for (int q = 0; q < NFRAG; q++)
            { acc[a][q][0]=0.f; acc[a][q][1]=0.f; acc[a][q][2]=0.f; acc[a][q][3]=0.f; }

    auto issue = [&](int t) {
        int buf = t & 1;
        #pragma unroll
        for (int j = 0; j < 2; j++) {
            int lin = tid + j*256; int r = lin >> 2, q = lin & 3;
            uint32_t off = (uint32_t)(buf*ASZ + r*RSU + q*4) * 4;
            size_t ao = (size_t)(m0 + r)*K2 + t*16 + q*4;
            cp_async16(bA + off, A_g + ao);
        }
        {
            int r = tid >> 2, q = tid & 3;
            uint32_t off = (uint32_t)(buf*BSZ + r*RSU + q*4) * 4;
            size_t bo = (size_t)(c0 + r)*K2 + t*16 + q*4;
            cp_async16(bBh + off, Bh_g + bo);
            cp_async16(bBl + off, Bl_g + bo);
        }
        CP_COMMIT();
    };

    auto compute = [&](int buf) {
        #pragma unroll
        for (int kk = 0; kk < 2; kk++) {
            uint32_t ah[2][4];
            #pragma unroll
            for (int mi = 0; mi < 2; mi++) {
                uint32_t off = (uint32_t)(buf*ASZ + (wm + mi*16 + rowA)*RSU + kk*8 + colA) * 4;
                ldsm4(ah[mi], bA + off);
            }
            #pragma unroll
            for (int np = 0; np < NFRAG/2; np++) {
                uint32_t off = (uint32_t)(buf*BSZ + (wn + np*16 + rowB)*RSU + kk*8 + colB) * 4;
                uint32_t th[4], tl[4];
                ldsm4(th, bBh + off);
                ldsm4(tl, bBl + off);
                #pragma unroll
                for (int sub = 0; sub < 2; sub++) {
                    int ni = np*2 + sub;
                    uint32_t bhp[2] = {th[sub*2], th[sub*2+1]};
                    uint32_t blp[2] = {tl[sub*2], tl[sub*2+1]};
                    #pragma unroll
                    for (int mi = 0; mi < 2; mi++) {
                        mma_f16(acc[mi][ni], ah[mi], bhp);
                        mma_f16(acc[mi][ni], ah[mi], blp);
                    }
                }
            }
        }
    };

    const int T = K / 32;
    issue(0);
    for (int t = 0; t < T; t++) {
        CP_WAIT0();
        __syncthreads();
        if (t + 1 < T) issue(t + 1);
        compute(t & 1);
    }
    __syncthreads();

    float* sbufS  = (float*)smem_u;
    float* sbufS2 = sbufS + 4*TN;
    __shared__ int isLast;

    #pragma unroll
    for (int ni = 0; ni < NFRAG; ni++) {
        int col = c0 + wn + ni*8 + lk*2;
        float2 b2 = *(const float2*)(bias + col);
        float s0 = 0.f, s1 = 0.f, q0 = 0.f, q1 = 0.f;
        #pragma unroll
        for (int mi = 0; mi < 2; mi++) {
            int row = m0 + wm + mi*16 + l4;
            float e0 = acc[mi][ni][0] + b2.x;
            float e1 = acc[mi][ni][1] + b2.y;
            float e2 = acc[mi][ni][2] + b2.x;
            float e3 = acc[mi][ni][3] + b2.y;
            *(float2*)(Y + (size_t)row * C + col)       = make_float2(e0, e1);
            *(float2*)(Y + (size_t)(row + 8) * C + col) = make_float2(e2, e3);
            s0 += e0 + e2; s1 += e1 + e3;
            q0 += e0*e0 + e2*e2; q1 += e1*e1 + e3*e3;
        }
        #pragma unroll
        for (int off = 16; off >= 4; off >>= 1) {
            s0 += __shfl_down_sync(0xffffffffu, s0, off);
            s1 += __shfl_down_sync(0xffffffffu, s1, off);
            q0 += __shfl_down_sync(0xffffffffu, q0, off);
            q1 += __shfl_down_sync(0xffffffffu, q1, off);
        }
        if (lane < 4) {
            int cb = wn + ni*8 + lk*2;
            sbufS [mw*TN + cb]     = s0;
            sbufS [mw*TN + cb + 1] = s1;
            sbufS2[mw*TN + cb]     = q0;
            sbufS2[mw*TN + cb + 1] = q1;
        }
    }
    __syncthreads();
    if (tid < TN) {
        float s = sbufS [tid] + sbufS [TN + tid] + sbufS [2*TN + tid] + sbufS [3*TN + tid];
        float q = sbufS2[tid] + sbufS2[TN + tid] + sbufS2[2*TN + tid] + sbufS2[3*TN + tid];
        pS [blockIdx.y * C + c0 + tid] = s;
        pS2[blockIdx.y * C + c0 + tid] = q;
        __threadfence();
    }
    __syncthreads();
    if (tid == 0) {
        int t = atomicAdd(&g_cnt, 1);
        isLast = (t == (int)(gridDim.x * gridDim.y) - 1);
    }
    __syncthreads();
    if (isLast) {
        __threadfence();
        const int npart = gridDim.y;
        for (int c = tid; c < C; c += 256) {
            float s = 0.f, q = 0.f;
            for (int p = 0; p < npart; p++) {
                s += pS [p * C + c];
                q += pS2[p * C + c];
            }
            float invM = 1.f / (float)MROWS;
            float mean = s * invM;
            float var  = fmaf(-mean, mean, q * invM);
            float inv  = rsqrtf(var + EPSV);
            float scv  = gc[c] * inv;
            scale[c] = scv;
            shift[c] = fmaf(-mean, scv, btc[c]);
        }
        if (tid == 0) g_cnt = 0;
    }
}

// ---------------- bnconvert_h: pure-streaming BN + leaky -> single fp16 ----------------
__global__ void __launch_bounds__(256) bnconvert_h_kernel(
    const float* __restrict__ Y, const float* __restrict__ scale,
    const float* __restrict__ shift, uint32_t* __restrict__ Ah, int C4)
{
    int idx = blockIdx.x * blockDim.x + threadIdx.x;
    int c4 = idx & (C4 - 1);
    float4 y  = ((const float4*)Y)[idx];
    float4 sc = __ldg(&((const float4*)scale)[c4]);
    float4 sh = __ldg(&((const float4*)shift)[c4]);
    float v0 = fmaf(y.x, sc.x, sh.x);
    float v1 = fmaf(y.y, sc.y, sh.y);
    float v2 = fmaf(y.z, sc.z, sh.z);
    float v3 = fmaf(y.w, sc.w, sh.w);
    v0 = v0 > 0.f ? v0 : v0 * SLOPE;
    v1 = v1 > 0.f ? v1 : v1 * SLOPE;
    v2 = v2 > 0.f ? v2 : v2 * SLOPE;
    v3 = v3 > 0.f ? v3 : v3 * SLOPE;
    ((uint2*)Ah)[idx] = make_uint2(pack_h(v0, v1), pack_h(v2, v3));
}

// ---------------- bnapply: pure-streaming BN -> out ----------------
__global__ void __launch_bounds__(256) bnapply_kernel(
    const float* __restrict__ Y, const float* __restrict__ scale,
    const float* __restrict__ shift, float* __restrict__ out, int C4)
{
    int idx = blockIdx.x * blockDim.x + threadIdx.x;
    int c4 = idx & (C4 - 1);
    float4 y  = ((const float4*)Y)[idx];
    float4 sc = __ldg(&((const float4*)scale)[c4]);
    float4 sh = __ldg(&((const float4*)shift)[c4]);
    float4 o;
    o.x = fmaf(y.x, sc.x, sh.x);
    o.y = fmaf(y.y, sc.y, sh.y);
    o.z = fmaf(y.z, sc.z, sh.z);
    o.w = fmaf(y.w, sc.w, sh.w);
    ((float4*)out)[idx] = o;
}

// ---------------- host ----------------
extern "C" void kernel_launch(void* const* d_in, const int* in_sizes, int n_in,
                              void* d_out, int out_size)
{
    const float* x   = (const float*)d_in[0];
    const float* Q   = (const float*)d_in[1];
    const float* W1  = (const float*)d_in[2];
    const float* b1  = (const float*)d_in[3];
    const float* g1  = (const float*)d_in[4];
    const float* bt1 = (const float*)d_in[5];
    const float* W2  = (const float*)d_in[6];
    const float* b2  = (const float*)d_in[7];
    const float* g2  = (const float*)d_in[8];
    const float* bt2 = (const float*)d_in[9];
    const float* W3  = (const float*)d_in[10];
    const float* b3  = (const float*)d_in[11];
    const float* g3  = (const float*)d_in[12];
    const float* bt3 = (const float*)d_in[13];
    float* out = (float*)d_out;

    float *En, *Y1, *Y2, *Y3, *pS, *pS2, *scale, *shift;
    uint32_t *Xthi, *Xtlo, *Gh, *Vh, *Axh;
    uint32_t *W1h, *W2h, *W3hi, *W3lo;
    cudaGetSymbolAddress((void**)&En,   g_En);
    cudaGetSymbolAddress((void**)&Xthi, g_Xthi);  cudaGetSymbolAddress((void**)&Xtlo, g_Xtlo);
    cudaGetSymbolAddress((void**)&Gh,   g_Gh);
    cudaGetSymbolAddress((void**)&Vh,   g_Vh);
    cudaGetSymbolAddress((void**)&Axh,  g_Axh);
    cudaGetSymbolAddress((void**)&W1h,  g_W1h);
    cudaGetSymbolAddress((void**)&W2h,  g_W2h);
    cudaGetSymbolAddress((void**)&W3hi, g_W3hi);  cudaGetSymbolAddress((void**)&W3lo, g_W3lo);
    cudaGetSymbolAddress((void**)&Y1, g_Y1);
    cudaGetSymbolAddress((void**)&Y2, g_Y2);
    cudaGetSymbolAddress((void**)&Y3, g_Y3);
    cudaGetSymbolAddress((void**)&pS, g_pS);      cudaGetSymbolAddress((void**)&pS2, g_pS2);
    cudaGetSymbolAddress((void**)&scale, g_scale); cudaGetSymbolAddress((void**)&shift, g_shift);

    const int SMEM64  = (2*ASZ  + 4*BSZ ) * 4;   // 40960 B
    const int SMEMBIG = (2*ASZB + 2*BSZB) * 4;   // 61440 B
    cudaFuncSetAttribute(vgemm_kernel,    cudaFuncAttributeMaxDynamicSharedMemorySize, SMEM64);
    cudaFuncSetAttribute(gemm_ps_kernel,  cudaFuncAttributeMaxDynamicSharedMemorySize, SMEM64);
    cudaFuncSetAttribute(gemm_big_kernel, cudaFuncAttributeMaxDynamicSharedMemorySize, SMEMBIG);

    // 1) prep (En/Xt + W converts + G build)
    prep_all_kernel<<<296, 256>>>(x, Q, En, Xthi, Xtlo,
                                  W1, W1h, W2, W2h, W3, W3hi, W3lo, Gh);

    // 2) V = En .* (G @ Xt^T) - pos  -> single fp16
    vgemm_kernel<<<dim3(4, 4, 16), 256, SMEM64>>>(Gh, Xthi, Xtlo, En, x, Vh);

    // 3) layer 1 (stats + finalize fused into GEMM)
    gemm_big_kernel<<<dim3(NH/128, MROWS/256), 512, SMEMBIG>>>(
        Vh, W1h, b1, Y1, pS, pS2, g1, bt1, scale, shift, VDIM, NH);
    bnconvert_h_kernel<<<MROWS*NH/4/256, 256>>>(Y1, scale, shift, Axh, NH/4);

    // 4) layer 2
    gemm_big_kernel<<<dim3(NH/128, MROWS/256), 512, SMEMBIG>>>(
        Axh, W2h, b2, Y2, pS, pS2, g2, bt2, scale, shift, NH, NH);
    bnconvert_h_kernel<<<MROWS*NH/4/256, 256>>>(Y2, scale, shift, Axh, NH/4);

    // 5) layer 3
    gemm_ps_kernel<<<dim3(NO/64, MROWS/128), 256, SMEM64>>>(
        Axh, W3hi, W3lo, b3, Y3, pS, pS2, g3, bt3, scale, shift, NH, NO);

    // 6) BN apply -> out
    bnapply_kernel<<<MROWS*NO/4/256, 256>>>(Y3, scale, shift, out, NO/4);
}